// round 7
// baseline (speedup 1.0000x reference)
#include <cuda_runtime.h>
#include <cstdint>

#define N_ATOMS 4096
#define L_WORDS 65536
#define DD 10
#define KS 23
#define KSPLIT 2
#define KCHUNK (N_ATOMS / KSPLIT)   // 2048
#define NT 256
#define SMEM_BYTES 81920            // 40 * (KCHUNK/8) * 8 = 80KB
#define MVROWS 8                    // rows per warp in mv
#define MVTILE 64                   // rows per mv tile (8 warps * 8 rows)

typedef unsigned long long ull;

// ---------------- scratch (device globals; no allocation allowed) ----------
__device__ float g_xs[N_ATOMS * DD];                 // xs, updated in place
__device__ ull   g_hs[8 * 5 * (N_ATOMS / 8)];        // hs f32x2, [k8][p][m/8]
__device__ uint4 g_Ab[(size_t)N_ATOMS * N_ATOMS / 8];// A bf16 (8 cols / uint4)
__device__ float g_pp[KSPLIT][N_ATOMS * DD];         // split-K partials
__device__ float g_cnn[2][L_WORDS * DD];             // CNN ping-pong
__device__ float g_comp[DD];
__device__ float g_hatt[DD];
__device__ float g_part[512 * DD];                   // attention block partials
__device__ float g_cpart[16 * DD];                   // compound partials
__device__ unsigned g_bar;                           // monotonic barrier counter

// ---------------- helpers ------------------------------------------------------
__device__ __forceinline__ ull pack2(float x, float y) {
    ull r; asm("mov.b64 %0, {%1, %2};" : "=l"(r) : "f"(x), "f"(y)); return r;
}
__device__ __forceinline__ void unpack2(ull v, float& x, float& y) {
    asm("mov.b64 {%0, %1}, %2;" : "=f"(x), "=f"(y) : "l"(v));
}
__device__ __forceinline__ void fma2(ull& d, ull a, ull b) {
    asm("fma.rn.f32x2 %0, %1, %2, %0;" : "+l"(d) : "l"(a), "l"(b));
}
__device__ __forceinline__ unsigned bfpack(float lo, float hi) {
    unsigned r;
    asm("cvt.rn.bf16x2.f32 %0, %1, %2;" : "=r"(r) : "f"(hi), "f"(lo));
    return r;
}

// ---------------- grid barrier (monotonic; replay-safe) ------------------------
__device__ __forceinline__ void gbar() {
    __syncthreads();
    if (threadIdx.x == 0) {
        __threadfence();
        unsigned old = atomicAdd(&g_bar, 1u);
        unsigned target = (old / gridDim.x + 1u) * gridDim.x;
        while (*(volatile unsigned*)&g_bar < target) { }
    }
    __syncthreads();
    __threadfence();
}

// ---------------- hs compute for one atom ---------------------------------------
__device__ __forceinline__ void hs_store(int m, const float* x,
                                         const float* Wgl, const float* bgl) {
    int k8 = m & 7, base = m >> 3;
#pragma unroll
    for (int p = 0; p < 5; p++) {
        float h0 = bgl[2 * p], h1 = bgl[2 * p + 1];
#pragma unroll
        for (int c = 0; c < DD; c++) {
            h0 = fmaf(x[c], Wgl[(2 * p) * DD + c], h0);
            h1 = fmaf(x[c], Wgl[(2 * p + 1) * DD + c], h1);
        }
        g_hs[(k8 * 5 + p) * (N_ATOMS / 8) + base] =
            pack2(fmaxf(h0, 0.f), fmaxf(h1, 0.f));
    }
}

// ---------------- GNN mv tile: 64 rows x 2048 cols (bf16 A) ---------------------
__device__ __forceinline__ void mv_tile(char* smem_raw, int u) {
    ull* sh = (ull*)smem_raw;   // [k8][p][j] j<256 : 80KB
    const int tid = threadIdx.x;
    const int rowblk = u & 63, kb = u >> 6;
    for (int i = tid; i < 40 * (KCHUNK / 8); i += NT) {
        int kp = i / (KCHUNK / 8), j = i % (KCHUNK / 8);
        sh[i] = g_hs[kp * (N_ATOMS / 8) + kb * (KCHUNK / 8) + j];
    }
    __syncthreads();

    const int warp = tid >> 5, lane = tid & 31;
    const int row0 = rowblk * MVTILE + warp * MVROWS;
    float* pout = g_pp[kb];
    const int rstride = N_ATOMS / 8;
    const uint4* Abase = g_Ab + (size_t)row0 * rstride + kb * (KCHUNK / 8);

    ull acc[MVROWS][5];
#pragma unroll
    for (int r = 0; r < MVROWS; r++)
#pragma unroll
        for (int p = 0; p < 5; p++) acc[r][p] = 0ull;

    for (int it = 0; it < KCHUNK / 256; it++) {   // 8 iters x 256 cols
        int q = it * 32 + lane;
        uint4 a[MVROWS];
#pragma unroll
        for (int r = 0; r < MVROWS; r++) a[r] = Abase[r * rstride + q];
#pragma unroll
        for (int k8 = 0; k8 < 8; k8++) {
            ull h[5];
#pragma unroll
            for (int p = 0; p < 5; p++)
                h[p] = sh[(k8 * 5 + p) * (KCHUNK / 8) + q];
#pragma unroll
            for (int r = 0; r < MVROWS; r++) {
                unsigned w = (k8 < 2) ? a[r].x : (k8 < 4) ? a[r].y
                           : (k8 < 6) ? a[r].z : a[r].w;
                float av = (k8 & 1) ? __uint_as_float(w & 0xffff0000u)
                                    : __uint_as_float(w << 16);
                ull v = pack2(av, av);
#pragma unroll
                for (int p = 0; p < 5; p++) fma2(acc[r][p], v, h[p]);
            }
        }
    }

#pragma unroll
    for (int r = 0; r < MVROWS; r++) {
        float f[DD];
#pragma unroll
        for (int p = 0; p < 5; p++) unpack2(acc[r][p], f[2 * p], f[2 * p + 1]);
#pragma unroll
        for (int d = 0; d < DD; d++)
#pragma unroll
            for (int o = 16; o > 0; o >>= 1)
                f[d] += __shfl_down_sync(0xffffffffu, f[d], o);
        if (lane == 0) {
#pragma unroll
            for (int d = 0; d < DD; d++)
                pout[(row0 + r) * DD + d] = f[d];
        }
    }
}

// ---------------- CNN tile: 512 rows, 2 rows/thread -----------------------------
__device__ __forceinline__ void cnn_tile(char* smem_raw, int t, int layer,
                                         const float* Wc, const float* bc) {
    float* sIn = (float*)smem_raw;                          // (512+22)*11 floats
    ull*   sW  = (ull*)(smem_raw + 24000);                  // 23*50 ull
    const int tid = threadIdx.x;
    const float* in = g_cnn[layer & 1];
    float*       o  = g_cnn[(layer & 1) ^ 1];
    const float* W  = Wc + layer * KS * KS;
    const float bias = bc[layer];

    for (int i = tid; i < KS * 50; i += NT) {
        int dl = i / 50, rem = i % 50, c = rem / 5, p = rem % 5;
        sW[i] = pack2(W[dl * KS + 11 + c - 2 * p], W[dl * KS + 11 + c - 2 * p - 1]);
    }
    int base = t * 512 - 11;
    for (int i = tid; i < (512 + 22) * DD; i += NT) {
        int rr = i / DD, c = i - rr * DD;
        int g = base + rr;
        sIn[rr * 11 + c] = (g >= 0 && g < L_WORDS) ? in[g * DD + c] : 0.f;
    }
    __syncthreads();

    ull b2 = pack2(bias, bias);
    ull acc[2][5];
#pragma unroll
    for (int r = 0; r < 2; r++)
#pragma unroll
        for (int p = 0; p < 5; p++) acc[r][p] = b2;
#pragma unroll 1
    for (int dl = 0; dl < KS; dl++) {
#pragma unroll
        for (int c = 0; c < DD; c++) {
            ull w[5];
#pragma unroll
            for (int p = 0; p < 5; p++) w[p] = sW[dl * 50 + c * 5 + p];
#pragma unroll
            for (int r = 0; r < 2; r++) {
                float xv = sIn[(tid + r * 256 + dl) * 11 + c];
                ull x2 = pack2(xv, xv);
#pragma unroll
                for (int p = 0; p < 5; p++) fma2(acc[r][p], x2, w[p]);
            }
        }
    }
#pragma unroll
    for (int r = 0; r < 2; r++) {
        int grow = t * 512 + tid + r * 256;
#pragma unroll
        for (int p = 0; p < 5; p++) {
            float v0, v1;
            unpack2(acc[r][p], v0, v1);
            o[grow * DD + 2 * p]     = fmaxf(v0, 0.f);
            o[grow * DD + 2 * p + 1] = fmaxf(v1, 0.f);
        }
    }
}

// ================== the one persistent kernel =================================
__global__ void __launch_bounds__(NT, 2) k_all(
    const int* __restrict__ fp, const float* __restrict__ A,
    const int* __restrict__ words, const float* __restrict__ embf,
    const float* __restrict__ embw,
    const float* __restrict__ Wg, const float* __restrict__ bg,
    const float* __restrict__ Wc, const float* __restrict__ bc,
    const float* __restrict__ Wat, const float* __restrict__ bat,
    const float* __restrict__ Wout, const float* __restrict__ bout,
    const float* __restrict__ Wint, const float* __restrict__ bint,
    float* __restrict__ out)
{
    extern __shared__ char smem_raw[];
    const int tid = threadIdx.x;
    const int bid = blockIdx.x;
    const int nb  = gridDim.x;
    const int gstride = nb * NT;

    // ---------- P0: gathers + hs layer0 (same m-partition) + A->bf16 ----------
    for (int m = bid * NT + tid; m < N_ATOMS; m += gstride) {
        float x[DD];
#pragma unroll
        for (int c = 0; c < DD; c++) {
            x[c] = embf[(size_t)fp[m] * DD + c];
            g_xs[m * DD + c] = x[c];
        }
        hs_store(m, x, Wg, bg);
    }
    for (int i = bid * NT + tid; i < L_WORDS * DD; i += gstride) {
        int n = i / DD, d = i - n * DD;
        g_cnn[0][i] = embw[(size_t)words[n] * DD + d];
    }
    {
        const float4* Af = (const float4*)A;
        for (int v = bid * NT + tid; v < N_ATOMS * N_ATOMS / 8; v += gstride) {
            float4 x0 = Af[2 * v], x1 = Af[2 * v + 1];
            uint4 o;
            o.x = bfpack(x0.x, x0.y);
            o.y = bfpack(x0.z, x0.w);
            o.z = bfpack(x1.x, x1.y);
            o.w = bfpack(x1.z, x1.w);
            g_Ab[v] = o;
        }
    }
    gbar();

    // ---------- 3 GNN layers; mv overlapped with the 3 CNN conv layers ----------
    for (int layer = 0; layer < 3; layer++) {
        // overlap phase: 128 mv tiles + 128 cnn tiles = 256 units (1 round)
        for (int u = bid; u < 256; u += nb) {
            if (u < 128) mv_tile(smem_raw, u);
            else cnn_tile(smem_raw, u - 128, layer, Wc, bc);
            __syncthreads();
        }
        gbar();

        // xs += P; hs for next layer (layers 0,1 only)
        if (layer < 2) {
            const float* Wgl = Wg + (layer + 1) * DD * DD;
            const float* bgl = bg + (layer + 1) * DD;
            for (int m = bid * NT + tid; m < N_ATOMS; m += gstride) {
                float x[DD];
#pragma unroll
                for (int c = 0; c < DD; c++) {
                    float v = g_xs[m * DD + c]
                            + g_pp[0][m * DD + c] + g_pp[1][m * DD + c];
                    g_xs[m * DD + c] = v;
                    x[c] = v;
                }
                hs_store(m, x, Wgl, bgl);
            }
            gbar();
        }
    }

    // ---------- compound partials: 16 tiles (xs3 = xs2 + P folded) ----------
    {
        float* red = (float*)smem_raw;
        for (int t = bid; t < 16; t += nb) {
            int n = t * 256 + tid;
            float acc[DD];
#pragma unroll
            for (int d = 0; d < DD; d++)
                acc[d] = g_xs[n * DD + d] + g_pp[0][n * DD + d] + g_pp[1][n * DD + d];
#pragma unroll
            for (int d = 0; d < DD; d++) red[tid * DD + d] = acc[d];
            __syncthreads();
            for (int s = 128; s > 0; s >>= 1) {
                if (tid < s) {
#pragma unroll
                    for (int d = 0; d < DD; d++)
                        red[tid * DD + d] += red[(tid + s) * DD + d];
                }
                __syncthreads();
            }
            if (tid < DD) g_cpart[t * DD + tid] = red[tid];
            __syncthreads();
        }
    }
    gbar();

    // ---------- compound finalize (block 0) ----------
    if (bid == 0) {
        __shared__ float scomp[DD];
        if (tid < DD) {
            float s = 0.f;
            for (int i = 0; i < 16; i++) s += g_cpart[i * DD + tid];
            scomp[tid] = s * (1.f / N_ATOMS);
        }
        __syncthreads();
        if (tid < DD) {
            g_comp[tid] = scomp[tid];
            float hv = bat[tid];
#pragma unroll
            for (int c = 0; c < DD; c++) hv = fmaf(scomp[c], Wat[tid * DD + c], hv);
            g_hatt[tid] = fmaxf(hv, 0.f);
        }
    }
    gbar();

    // ---------- attention pass: grid-stride over words ----------
    {
        float* sWat = (float*)smem_raw;          // 100
        float* sbv  = sWat + DD * DD;            // 10
        float* shv  = sbv + DD;                  // 10
        float* red  = shv + DD + 2;              // 256*10
        if (tid < DD * DD) sWat[tid] = Wat[tid];
        if (tid < DD) { sbv[tid] = bat[tid]; shv[tid] = g_hatt[tid]; }
        __syncthreads();

        float acc[DD];
#pragma unroll
        for (int d = 0; d < DD; d++) acc[d] = 0.f;
        const float* in = g_cnn[1];   // CNN output after 3 layers (0->1->0->1)
        for (int l = bid * NT + tid; l < L_WORDS; l += gstride) {
            float x[DD];
#pragma unroll
            for (int c = 0; c < DD; c++) x[c] = in[l * DD + c];
            float hp[DD], wl = 0.f;
#pragma unroll
            for (int u = 0; u < DD; u++) {
                float v = sbv[u];
#pragma unroll
                for (int c = 0; c < DD; c++) v = fmaf(x[c], sWat[u * DD + c], v);
                v = fmaxf(v, 0.f);
                hp[u] = v;
                wl = fmaf(shv[u], v, wl);
            }
            wl = tanhf(wl);
#pragma unroll
            for (int d = 0; d < DD; d++) acc[d] = fmaf(wl, hp[d], acc[d]);
        }
#pragma unroll
        for (int d = 0; d < DD; d++) red[tid * DD + d] = acc[d];
        __syncthreads();
        for (int s = 128; s > 0; s >>= 1) {
            if (tid < s) {
#pragma unroll
                for (int d = 0; d < DD; d++)
                    red[tid * DD + d] += red[(tid + s) * DD + d];
            }
            __syncthreads();
        }
        if (tid < DD) g_part[bid * DD + tid] = red[tid];
    }
    gbar();

    // ---------- final: reduce g_part over nb blocks + fusion MLP (block 0) ----
    if (bid == 0) {
        float* red = (float*)smem_raw;
        float* cat = red + NT * DD;
        float acc[DD];
#pragma unroll
        for (int d = 0; d < DD; d++) acc[d] = 0.f;
        for (int b = tid; b < nb; b += NT)
#pragma unroll
            for (int d = 0; d < DD; d++) acc[d] += g_part[b * DD + d];
#pragma unroll
        for (int d = 0; d < DD; d++) red[tid * DD + d] = acc[d];
        __syncthreads();
        for (int s = 128; s > 0; s >>= 1) {
            if (tid < s) {
#pragma unroll
                for (int d = 0; d < DD; d++)
                    red[tid * DD + d] += red[(tid + s) * DD + d];
            }
            __syncthreads();
        }
        if (tid < DD) cat[tid] = g_comp[tid];
        if (tid >= DD && tid < 20) cat[tid] = red[tid - DD] * (1.f / L_WORDS);
        __syncthreads();
        if (tid < 32) {
            for (int j = 0; j < 3; j++) {
                float v = 0.f;
                if (tid < 20) {
                    v = bout[j * 20 + tid];
                    for (int c = 0; c < 20; c++)
                        v = fmaf(cat[c], Wout[j * 400 + tid * 20 + c], v);
                    v = fmaxf(v, 0.f);
                }
                __syncwarp();
                if (tid < 20) cat[tid] = v;
                __syncwarp();
            }
            if (tid < 2) {
                float v = bint[tid];
                for (int c = 0; c < 20; c++) v = fmaf(cat[c], Wint[tid * 20 + c], v);
                out[tid] = v;
            }
        }
    }
}

// ---------------- launch ------------------------------------------------------
extern "C" void kernel_launch(void* const* d_in, const int* in_sizes, int n_in,
                              void* d_out, int out_size) {
    const int*   fp    = (const int*)d_in[0];
    const float* A     = (const float*)d_in[1];
    const int*   words = (const int*)d_in[2];
    const float* embf  = (const float*)d_in[3];
    const float* embw  = (const float*)d_in[4];
    const float* Wg    = (const float*)d_in[5];
    const float* bg    = (const float*)d_in[6];
    const float* Wc    = (const float*)d_in[7];
    const float* bc    = (const float*)d_in[8];
    const float* Wat   = (const float*)d_in[9];
    const float* bat   = (const float*)d_in[10];
    const float* Wout  = (const float*)d_in[11];
    const float* bout  = (const float*)d_in[12];
    const float* Wint  = (const float*)d_in[13];
    const float* bint  = (const float*)d_in[14];
    float* out = (float*)d_out;

    cudaFuncSetAttribute(k_all, cudaFuncAttributeMaxDynamicSharedMemorySize, SMEM_BYTES);
    int dev = 0;
    cudaGetDevice(&dev);
    int nsm = 0;
    cudaDeviceGetAttribute(&nsm, cudaDevAttrMultiProcessorCount, dev);
    int per = 0;
    cudaOccupancyMaxActiveBlocksPerMultiprocessor(&per, k_all, NT, SMEM_BYTES);
    if (per < 1) per = 1;
    if (per > 2) per = 2;
    int grid = nsm * per;   // all blocks guaranteed co-resident

    k_all<<<grid, NT, SMEM_BYTES>>>(fp, A, words, embf, embw, Wg, bg, Wc, bc,
                                    Wat, bat, Wout, bout, Wint, bint, out);
}